// round 5
// baseline (speedup 1.0000x reference)
#include <cuda_runtime.h>

#define MAXN 100000
#define DDIM 64

// Scratch (device globals: allocation-free per harness rules)
__device__ float g_agg[MAXN * DDIM];   // per-layer aggregation accumulator
__device__ float g_h[MAXN * DDIM];     // hidden activations after layer 1
__device__ float g_cnt[MAXN];          // in-degree (float), computed once
__device__ int   g_idx64;              // 1 if edge_index is int64, 0 if int32

// ---------------------------------------------------------------------------
// Detect edge_index dtype. If the buffer is int32, reading it as int64 fuses
// two indices -> values far outside [0, N). 32 probes make misdetection
// probability ~(N/2^32)^32 ~ 0.
// ---------------------------------------------------------------------------
__global__ void detect_kernel(const long long* __restrict__ ei, int nprobe, int N) {
    if (threadIdx.x == 0 && blockIdx.x == 0) {
        int is64 = 1;
        for (int i = 0; i < nprobe; i++) {
            long long v = ei[i];
            if (v < 0 || v >= (long long)N) { is64 = 0; break; }
        }
        g_idx64 = is64;
    }
}

// ---------------------------------------------------------------------------
// Zero the aggregation buffer (and optionally the count buffer)
// ---------------------------------------------------------------------------
__global__ void zero_kernel(int nf4, int ncnt) {
    int stride = gridDim.x * blockDim.x;
    int tid = blockIdx.x * blockDim.x + threadIdx.x;
    float4 z = make_float4(0.f, 0.f, 0.f, 0.f);
    float4* a = reinterpret_cast<float4*>(g_agg);
    for (int k = tid; k < nf4; k += stride) a[k] = z;
    for (int k = tid; k < ncnt; k += stride) g_cnt[k] = 0.f;
}

// ---------------------------------------------------------------------------
// Edge scatter: 16 threads per edge, each owns one float4 column.
//   g_agg[dst] += x[src] * edge_weight       (vector atomic, no return -> RED)
//   g_cnt[dst] += 1                          (only on first pass)
// wp (weight_param) is folded into the combine-stage scale, not applied here.
// ---------------------------------------------------------------------------
template <bool COUNT>
__global__ __launch_bounds__(256)
void scatter_kernel(const float4* __restrict__ x4,
                    const void* __restrict__ ei_raw,
                    const float* __restrict__ ew,
                    int E) {
    long long t = (long long)blockIdx.x * 256 + threadIdx.x;
    int e = (int)(t >> 4);
    if (e >= E) return;
    int lane = (int)t & 15;

    int src, dst;
    if (g_idx64) {
        const long long* ei = (const long long*)ei_raw;
        src = (int)ei[e];
        dst = (int)ei[(long long)E + e];
    } else {
        const int* ei = (const int*)ei_raw;
        src = ei[e];
        dst = ei[E + e];
    }
    float w = ew[e];

    if (COUNT && lane == 0) {
        atomicAdd(&g_cnt[dst], 1.0f);
    }

    float4 v = x4[(long long)src * 16 + lane];
    v.x *= w; v.y *= w; v.z *= w; v.w *= w;

    float4* p = reinterpret_cast<float4*>(&g_agg[(long long)dst * 64 + lane * 4]);
#if __CUDA_ARCH__ >= 900
    atomicAdd(p, v);               // vector red.global.add.v4.f32
#else
    atomicAdd(&p->x, v.x);
    atomicAdd(&p->y, v.y);
    atomicAdd(&p->z, v.z);
    atomicAdd(&p->w, v.w);
#endif
}

// ---------------------------------------------------------------------------
// Combine: per 64-node tile
//   out[n] = in[n] @ Ws^T + bs + (agg[n] * wp / max(cnt[n],1)) @ Wn^T + bn
//   optional ReLU.
// 256 threads, 4x4 register tile each (64 nodes x 64 outputs per block).
// ---------------------------------------------------------------------------
template <bool RELU>
__global__ __launch_bounds__(256)
void combine_kernel(const float* __restrict__ in,
                    const float* __restrict__ Ws, const float* __restrict__ bs,
                    const float* __restrict__ Wn, const float* __restrict__ bn,
                    const float* __restrict__ wp,
                    float* __restrict__ out, int N) {
    __shared__ float sWs[64 * 64];  // transposed: sWs[j*64+i] = Ws[i][j]
    __shared__ float sWn[64 * 64];
    __shared__ float sT[64 * 64];   // natural:    sT[n*64+j]

    int tid = threadIdx.x;
    int n0 = blockIdx.x * 64;
    float wpv = wp[0];

    #pragma unroll
    for (int r = 0; r < 16; r++) {
        int idx = r * 256 + tid;
        int j = idx >> 6, i = idx & 63;
        sWs[idx] = Ws[i * 64 + j];
        sWn[idx] = Wn[i * 64 + j];
    }
    #pragma unroll
    for (int r = 0; r < 16; r++) {
        int idx = r * 256 + tid;
        int n = idx >> 6, j = idx & 63;
        int gn = n0 + n;
        sT[idx] = (gn < N) ? in[(long long)gn * 64 + j] : 0.f;
    }
    __syncthreads();

    int tn = tid >> 4, ti = tid & 15;  // node group / output group
    float acc[4][4];
    #pragma unroll
    for (int u = 0; u < 4; u++)
        #pragma unroll
        for (int v = 0; v < 4; v++) acc[u][v] = 0.f;

    // Pass 1: in @ Ws^T
    #pragma unroll 8
    for (int j = 0; j < 64; j++) {
        float a[4], b[4];
        #pragma unroll
        for (int u = 0; u < 4; u++) a[u] = sT[(tn + 16 * u) * 64 + j];
        #pragma unroll
        for (int v = 0; v < 4; v++) b[v] = sWs[j * 64 + ti + 16 * v];
        #pragma unroll
        for (int u = 0; u < 4; u++)
            #pragma unroll
            for (int v = 0; v < 4; v++) acc[u][v] += a[u] * b[v];
    }
    __syncthreads();

    // Load agg tile, scaled by wp / max(cnt,1)
    #pragma unroll
    for (int r = 0; r < 16; r++) {
        int idx = r * 256 + tid;
        int n = idx >> 6, j = idx & 63;
        int gn = n0 + n;
        float val = 0.f;
        if (gn < N) {
            float inv = wpv / fmaxf(g_cnt[gn], 1.0f);
            val = g_agg[(long long)gn * 64 + j] * inv;
        }
        sT[idx] = val;
    }
    __syncthreads();

    // Pass 2: agg @ Wn^T
    #pragma unroll 8
    for (int j = 0; j < 64; j++) {
        float a[4], b[4];
        #pragma unroll
        for (int u = 0; u < 4; u++) a[u] = sT[(tn + 16 * u) * 64 + j];
        #pragma unroll
        for (int v = 0; v < 4; v++) b[v] = sWn[j * 64 + ti + 16 * v];
        #pragma unroll
        for (int u = 0; u < 4; u++)
            #pragma unroll
            for (int v = 0; v < 4; v++) acc[u][v] += a[u] * b[v];
    }

    // Store with bias (+ReLU)
    #pragma unroll
    for (int u = 0; u < 4; u++) {
        int gn = n0 + tn + 16 * u;
        if (gn < N) {
            #pragma unroll
            for (int v = 0; v < 4; v++) {
                int i = ti + 16 * v;
                float val = acc[u][v] + bs[i] + bn[i];
                if (RELU) val = fmaxf(val, 0.f);
                out[(long long)gn * 64 + i] = val;
            }
        }
    }
}

// ---------------------------------------------------------------------------
// Launch: detect -> zero -> scatter(x)+count -> combine1(relu->h)
//         -> zero -> scatter(h) -> combine2(->out)
// ---------------------------------------------------------------------------
extern "C" void kernel_launch(void* const* d_in, const int* in_sizes, int n_in,
                              void* d_out, int out_size) {
    const float* x       = (const float*)d_in[0];
    const void*  ei      = d_in[1];                 // int32 or int64 (detected)
    const float* ew      = (const float*)d_in[2];
    const float* Ws1 = (const float*)d_in[3];
    const float* bs1 = (const float*)d_in[4];
    const float* Wn1 = (const float*)d_in[5];
    const float* bn1 = (const float*)d_in[6];
    const float* wp1 = (const float*)d_in[7];
    const float* Ws2 = (const float*)d_in[8];
    const float* bs2 = (const float*)d_in[9];
    const float* Wn2 = (const float*)d_in[10];
    const float* bn2 = (const float*)d_in[11];
    const float* wp2 = (const float*)d_in[12];

    int N = in_sizes[0] / DDIM;
    int E = in_sizes[2];
    float* out = (float*)d_out;

    // Resolve DEVICE address of g_h (host shadow symbol is not a device ptr).
    // cudaGetSymbolAddress is a pure query: no alloc, no stream op.
    void* h_ptr_v = nullptr;
    cudaGetSymbolAddress(&h_ptr_v, g_h);
    float* h_ptr = (float*)h_ptr_v;

    int nf4 = N * (DDIM / 4);
    int zero_blocks = (nf4 + 255) / 256;
    long long sthreads = (long long)E * 16;
    int sblocks = (int)((sthreads + 255) / 256);
    int cblocks = (N + 63) / 64;
    int nprobe = (E > 32) ? 32 : E;

    detect_kernel<<<1, 32>>>((const long long*)ei, nprobe, N);

    // Layer 1
    zero_kernel<<<zero_blocks, 256>>>(nf4, N);
    scatter_kernel<true><<<sblocks, 256>>>((const float4*)x, ei, ew, E);
    combine_kernel<true><<<cblocks, 256>>>(x, Ws1, bs1, Wn1, bn1, wp1, h_ptr, N);

    // Layer 2
    zero_kernel<<<zero_blocks, 256>>>(nf4, 0);
    scatter_kernel<false><<<sblocks, 256>>>((const float4*)h_ptr, ei, ew, E);
    combine_kernel<false><<<cblocks, 256>>>(h_ptr, Ws2, bs2, Wn2, bn2, wp2, out, N);
}

// round 6
// speedup vs baseline: 1.0765x; 1.0765x over previous
#include <cuda_runtime.h>

#define MAXN 100000
#define DDIM 64

// Scratch (device globals: allocation-free per harness rules)
__device__ float g_agg[MAXN * DDIM];   // per-layer aggregation accumulator
__device__ float g_h[MAXN * DDIM];     // hidden activations after layer 1
__device__ float g_cnt[MAXN];          // in-degree (float), computed once
__device__ int   g_idx64;              // 1 if edge_index is int64, 0 if int32

// ---------------------------------------------------------------------------
// Detect edge_index dtype (int32 read as int64 -> values far outside [0,N)).
// ---------------------------------------------------------------------------
__global__ void detect_kernel(const long long* __restrict__ ei, int nprobe, int N) {
    if (threadIdx.x == 0 && blockIdx.x == 0) {
        int is64 = 1;
        for (int i = 0; i < nprobe; i++) {
            long long v = ei[i];
            if (v < 0 || v >= (long long)N) { is64 = 0; break; }
        }
        g_idx64 = is64;
    }
}

// ---------------------------------------------------------------------------
// Zero the aggregation buffer (and optionally the count buffer)
// ---------------------------------------------------------------------------
__global__ void zero_kernel(int nf4, int ncnt) {
    int stride = gridDim.x * blockDim.x;
    int tid = blockIdx.x * blockDim.x + threadIdx.x;
    float4 z = make_float4(0.f, 0.f, 0.f, 0.f);
    float4* a = reinterpret_cast<float4*>(g_agg);
    for (int k = tid; k < nf4; k += stride) a[k] = z;
    for (int k = tid; k < ncnt; k += stride) g_cnt[k] = 0.f;
}

// ---------------------------------------------------------------------------
// Edge scatter (UNCHANGED from passing R5 kernel): 16 threads/edge, vector RED.
// ---------------------------------------------------------------------------
template <bool COUNT>
__global__ __launch_bounds__(256)
void scatter_kernel(const float4* __restrict__ x4,
                    const void* __restrict__ ei_raw,
                    const float* __restrict__ ew,
                    int E) {
    long long t = (long long)blockIdx.x * 256 + threadIdx.x;
    int e = (int)(t >> 4);
    if (e >= E) return;
    int lane = (int)t & 15;

    int src, dst;
    if (g_idx64) {
        const long long* ei = (const long long*)ei_raw;
        src = (int)ei[e];
        dst = (int)ei[(long long)E + e];
    } else {
        const int* ei = (const int*)ei_raw;
        src = ei[e];
        dst = ei[E + e];
    }
    float w = ew[e];

    if (COUNT && lane == 0) {
        atomicAdd(&g_cnt[dst], 1.0f);
    }

    float4 v = x4[(long long)src * 16 + lane];
    v.x *= w; v.y *= w; v.z *= w; v.w *= w;

    float4* p = reinterpret_cast<float4*>(&g_agg[(long long)dst * 64 + lane * 4]);
#if __CUDA_ARCH__ >= 900
    atomicAdd(p, v);               // vector red.global.add.v4.f32
#else
    atomicAdd(&p->x, v.x);
    atomicAdd(&p->y, v.y);
    atomicAdd(&p->z, v.z);
    atomicAdd(&p->w, v.w);
#endif
}

// ---------------------------------------------------------------------------
// Combine v2: fully LDS.128-vectorized dual GEMM.
//   out[n] = in[n] @ Ws^T + bs + (agg[n] * wp / max(cnt[n],1)) @ Wn^T + bn
// Block: 64 nodes x 64 outputs, 256 threads.
// Thread (tn,ti): rows 4*tn..4*tn+3, cols 4*ti..4*ti+3.
//   a: float4 over j from natural tile sT[n][j]       (broadcast, free)
//   b: float4 over i from transposed sW[j][i]          (4-stride, conflict-free)
// 8 LDS.128 per 64 FFMA (was 32 scalar LDS). W buffer reused across passes.
// ---------------------------------------------------------------------------
template <bool RELU>
__global__ __launch_bounds__(256, 4)
void combine_kernel(const float* __restrict__ in,
                    const float* __restrict__ Ws, const float* __restrict__ bs,
                    const float* __restrict__ Wn, const float* __restrict__ bn,
                    const float* __restrict__ wp,
                    float* __restrict__ out, int N) {
    __shared__ float sW[64 * 64];   // transposed: sW[j*64+i] = W[i][j]
    __shared__ float sT[64 * 64];   // natural:    sT[n*64+j]

    int tid = threadIdx.x;
    int n0 = blockIdx.x * 64;
    float wpv = wp[0];
    int tn = tid >> 4, ti = tid & 15;

    // --- load Ws transposed ---
    #pragma unroll
    for (int r = 0; r < 16; r++) {
        int idx = r * 256 + tid;
        int j = idx >> 6, i = idx & 63;
        sW[idx] = Ws[i * 64 + j];
    }
    // --- load input tile (vectorized, coalesced) ---
    #pragma unroll
    for (int r = 0; r < 4; r++) {
        int idx = r * 256 + tid;            // float4 index: 1024 per tile
        int n = idx >> 4, q = idx & 15;
        int gn = n0 + n;
        float4 v = make_float4(0.f, 0.f, 0.f, 0.f);
        if (gn < N) v = reinterpret_cast<const float4*>(in)[(long long)gn * 16 + q];
        reinterpret_cast<float4*>(sT)[idx] = v;
    }
    __syncthreads();

    float acc[4][4];
    #pragma unroll
    for (int u = 0; u < 4; u++)
        #pragma unroll
        for (int v = 0; v < 4; v++) acc[u][v] = 0.f;

    // --- pass 1: in @ Ws^T ---
    #pragma unroll
    for (int j4 = 0; j4 < 64; j4 += 4) {
        float4 a[4], b[4];
        #pragma unroll
        for (int u = 0; u < 4; u++)
            a[u] = *reinterpret_cast<const float4*>(&sT[(4 * tn + u) * 64 + j4]);
        #pragma unroll
        for (int jj = 0; jj < 4; jj++)
            b[jj] = *reinterpret_cast<const float4*>(&sW[(j4 + jj) * 64 + 4 * ti]);
        #pragma unroll
        for (int u = 0; u < 4; u++) {
            acc[u][0] += a[u].x * b[0].x + a[u].y * b[1].x + a[u].z * b[2].x + a[u].w * b[3].x;
            acc[u][1] += a[u].x * b[0].y + a[u].y * b[1].y + a[u].z * b[2].y + a[u].w * b[3].y;
            acc[u][2] += a[u].x * b[0].z + a[u].y * b[1].z + a[u].z * b[2].z + a[u].w * b[3].z;
            acc[u][3] += a[u].x * b[0].w + a[u].y * b[1].w + a[u].z * b[2].w + a[u].w * b[3].w;
        }
    }
    __syncthreads();   // everyone done reading sW/sT before overwrite

    // --- reload: Wn transposed + scaled agg tile ---
    #pragma unroll
    for (int r = 0; r < 16; r++) {
        int idx = r * 256 + tid;
        int j = idx >> 6, i = idx & 63;
        sW[idx] = Wn[i * 64 + j];
    }
    #pragma unroll
    for (int r = 0; r < 4; r++) {
        int idx = r * 256 + tid;
        int n = idx >> 4, q = idx & 15;
        int gn = n0 + n;
        float4 v = make_float4(0.f, 0.f, 0.f, 0.f);
        if (gn < N) {
            float inv = wpv / fmaxf(g_cnt[gn], 1.0f);
            v = reinterpret_cast<const float4*>(g_agg)[(long long)gn * 16 + q];
            v.x *= inv; v.y *= inv; v.z *= inv; v.w *= inv;
        }
        reinterpret_cast<float4*>(sT)[idx] = v;
    }
    __syncthreads();

    // --- pass 2: agg @ Wn^T ---
    #pragma unroll
    for (int j4 = 0; j4 < 64; j4 += 4) {
        float4 a[4], b[4];
        #pragma unroll
        for (int u = 0; u < 4; u++)
            a[u] = *reinterpret_cast<const float4*>(&sT[(4 * tn + u) * 64 + j4]);
        #pragma unroll
        for (int jj = 0; jj < 4; jj++)
            b[jj] = *reinterpret_cast<const float4*>(&sW[(j4 + jj) * 64 + 4 * ti]);
        #pragma unroll
        for (int u = 0; u < 4; u++) {
            acc[u][0] += a[u].x * b[0].x + a[u].y * b[1].x + a[u].z * b[2].x + a[u].w * b[3].x;
            acc[u][1] += a[u].x * b[0].y + a[u].y * b[1].y + a[u].z * b[2].y + a[u].w * b[3].y;
            acc[u][2] += a[u].x * b[0].z + a[u].y * b[1].z + a[u].z * b[2].z + a[u].w * b[3].z;
            acc[u][3] += a[u].x * b[0].w + a[u].y * b[1].w + a[u].z * b[2].w + a[u].w * b[3].w;
        }
    }

    // --- epilogue: bias (+ReLU), vectorized store ---
    float4 bsv = reinterpret_cast<const float4*>(bs)[ti];
    float4 bnv = reinterpret_cast<const float4*>(bn)[ti];
    float4 bias = make_float4(bsv.x + bnv.x, bsv.y + bnv.y,
                              bsv.z + bnv.z, bsv.w + bnv.w);
    #pragma unroll
    for (int u = 0; u < 4; u++) {
        int gn = n0 + 4 * tn + u;
        if (gn < N) {
            float4 val;
            val.x = acc[u][0] + bias.x;
            val.y = acc[u][1] + bias.y;
            val.z = acc[u][2] + bias.z;
            val.w = acc[u][3] + bias.w;
            if (RELU) {
                val.x = fmaxf(val.x, 0.f); val.y = fmaxf(val.y, 0.f);
                val.z = fmaxf(val.z, 0.f); val.w = fmaxf(val.w, 0.f);
            }
            reinterpret_cast<float4*>(out)[(long long)gn * 16 + ti] = val;
        }
    }
}

// ---------------------------------------------------------------------------
// Launch: detect -> zero -> scatter(x)+count -> combine1(relu->h)
//         -> zero -> scatter(h) -> combine2(->out)
// ---------------------------------------------------------------------------
extern "C" void kernel_launch(void* const* d_in, const int* in_sizes, int n_in,
                              void* d_out, int out_size) {
    const float* x       = (const float*)d_in[0];
    const void*  ei      = d_in[1];                 // int32 or int64 (detected)
    const float* ew      = (const float*)d_in[2];
    const float* Ws1 = (const float*)d_in[3];
    const float* bs1 = (const float*)d_in[4];
    const float* Wn1 = (const float*)d_in[5];
    const float* bn1 = (const float*)d_in[6];
    const float* wp1 = (const float*)d_in[7];
    const float* Ws2 = (const float*)d_in[8];
    const float* bs2 = (const float*)d_in[9];
    const float* Wn2 = (const float*)d_in[10];
    const float* bn2 = (const float*)d_in[11];
    const float* wp2 = (const float*)d_in[12];

    int N = in_sizes[0] / DDIM;
    int E = in_sizes[2];
    float* out = (float*)d_out;

    // Resolve DEVICE address of g_h (host shadow symbol is not a device ptr).
    void* h_ptr_v = nullptr;
    cudaGetSymbolAddress(&h_ptr_v, g_h);
    float* h_ptr = (float*)h_ptr_v;

    int nf4 = N * (DDIM / 4);
    int zero_blocks = (nf4 + 255) / 256;
    long long sthreads = (long long)E * 16;
    int sblocks = (int)((sthreads + 255) / 256);
    int cblocks = (N + 63) / 64;
    int nprobe = (E > 32) ? 32 : E;

    detect_kernel<<<1, 32>>>((const long long*)ei, nprobe, N);

    // Layer 1
    zero_kernel<<<zero_blocks, 256>>>(nf4, N);
    scatter_kernel<true><<<sblocks, 256>>>((const float4*)x, ei, ew, E);
    combine_kernel<true><<<cblocks, 256>>>(x, Ws1, bs1, Wn1, bn1, wp1, h_ptr, N);

    // Layer 2
    zero_kernel<<<zero_blocks, 256>>>(nf4, 0);
    scatter_kernel<false><<<sblocks, 256>>>((const float4*)h_ptr, ei, ew, E);
    combine_kernel<false><<<cblocks, 256>>>(h_ptr, Ws2, bs2, Wn2, bn2, wp2, out, N);
}